// round 5
// baseline (speedup 1.0000x reference)
#include <cuda_runtime.h>
#include <cstdint>

#define B_      2
#define I_      1024
#define J_      1024
#define C_      64
#define TJ      64
#define NT      (J_/TJ)     // 16
#define ROWS    2           // rows per block; 2 warps per row (j-split)
#define THREADS 128
#define KPAD    17          // float4 per K row in smem (conflict-free)

__device__ __forceinline__ float tanh_apx(float x) {
    float y; asm("tanh.approx.f32 %0, %1;" : "=f"(y) : "f"(x)); return y;
}
__device__ __forceinline__ void cp16(uint32_t s, const void* g) {
    asm volatile("cp.async.cg.shared.global [%0], [%1], 16;" :: "r"(s), "l"(g));
}
__device__ __forceinline__ void cp_commit() { asm volatile("cp.async.commit_group;"); }
template<int N> __device__ __forceinline__ void cp_wait() {
    asm volatile("cp.async.wait_group %0;" :: "n"(N));
}

__global__ __launch_bounds__(THREADS, 6)
void fused_attn_mlp_kernel(const float* __restrict__ Q,
                           const float* __restrict__ K,
                           const float* __restrict__ bias,
                           const float* __restrict__ mask,
                           float* __restrict__ out,      // [B,I,C]
                           float* __restrict__ attn)     // [B,I,J]
{
    __shared__ __align__(16) float4 kbuf[2][TJ * KPAD];   // 2 x 17KB
    __shared__ __align__(16) float4 sq[ROWS][16];         // 0.5*Q rows
    __shared__ __align__(16) float4 sbv[16];              // 0.5*bias
    __shared__ __align__(16) float  sacc[ROWS][2][C_];    // per (row, jh) partials
    __shared__ float smsum[ROWS][2];

    const int tid  = threadIdx.x;
    const int lane = tid & 31;
    const int w    = tid >> 5;            // 0..3
    const int rowl = w >> 1;              // local row 0/1
    const int jh   = w & 1;               // which 32-j half of the tile
    const int half = lane >> 4;           // channel half: 0 -> ch0-31, 1 -> ch32-63
    const int lj   = lane & 15;           // j within 16-group
    const int row  = blockIdx.x * ROWS + rowl;
    const int b    = row >> 10;
    const int h8   = half * 8;            // float4 offset of this channel half

    // stage 0.5*bias and 0.5*Q rows
    if (tid < C_) ((float*)sbv)[tid] = 0.5f * bias[tid];
    if (tid < ROWS * C_ - C_ * 0) {}      // (no-op; keep flow simple)
    {
        int idx = tid;                    // ROWS*C_ = 128 = THREADS
        int r = idx >> 6, c = idx & 63;
        ((float*)sq)[idx] = 0.5f * Q[(size_t)(blockIdx.x * ROWS + r) * C_ + c];
    }

    const uint32_t sb0 = (uint32_t)__cvta_generic_to_shared(&kbuf[0][0]);
    const uint32_t sb1 = (uint32_t)__cvta_generic_to_shared(&kbuf[1][0]);
    const float4* Kb = (const float4*)K + (size_t)b * J_ * 16;

    // prefetch tile 0: TJ*16 = 1024 float4 / 128 thr = 8 per thread
    #pragma unroll
    for (int p = 0; p < (TJ * 16) / THREADS; ++p) {
        int idx = tid + p * THREADS;
        int r = idx >> 4, c = idx & 15;
        cp16(sb0 + (uint32_t)(r * KPAD + c) * 16, Kb + (size_t)r * 16 + c);
    }
    cp_commit();
    __syncthreads();

    float ssum = 0.f;
    #pragma unroll
    for (int c = 0; c < C_; ++c) ssum += ((const float*)sbv)[c];

    float4 acc[8];
    #pragma unroll
    for (int c = 0; c < 8; ++c) acc[c] = make_float4(0.f, 0.f, 0.f, 0.f);
    float msum = 0.f;

    const float* mrow = mask + (size_t)row * J_;
    float*       arow = attn + (size_t)row * J_;
    const float4* qp  = &sq[rowl][h8];
    const float4* bp  = &sbv[h8];

    for (int t = 0; t < NT; ++t) {
        // this warp's masks for the tile (independent of smem state)
        const float m0 = mrow[t * TJ + jh * 32 + lj];
        const float m1 = mrow[t * TJ + jh * 32 + 16 + lj];

        if (t + 1 < NT) {
            const float4* src = Kb + (size_t)(t + 1) * TJ * 16;
            uint32_t dst = ((t + 1) & 1) ? sb1 : sb0;
            #pragma unroll
            for (int p = 0; p < (TJ * 16) / THREADS; ++p) {
                int idx = tid + p * THREADS;
                int r = idx >> 4, c = idx & 15;
                cp16(dst + (uint32_t)(r * KPAD + c) * 16, src + (size_t)r * 16 + c);
            }
            cp_commit();
            cp_wait<1>();
        } else {
            cp_wait<0>();
        }
        __syncthreads();

        const float4* kb = kbuf[t & 1];

        #pragma unroll
        for (int u = 0; u < 2; ++u) {
            const int jj = jh * 32 + u * 16 + lj;      // j within tile
            const float m  = (u == 0) ? m0 : m1;
            const float mh = 0.5f * m;
            const float4* kr = kb + jj * KPAD + h8;

            float hs0 = 0.f, hs1 = 0.f, hs2 = 0.f, hs3 = 0.f;
            #pragma unroll
            for (int c = 0; c < 8; ++c) {
                const float4 k4 = kr[c];
                const float4 q4 = qp[c];   // broadcast LDS
                const float4 b4 = bp[c];   // broadcast LDS
                const float h0 = fmaf(q4.x, k4.x, b4.x);
                const float h1 = fmaf(q4.y, k4.y, b4.y);
                const float h2 = fmaf(q4.z, k4.z, b4.z);
                const float h3 = fmaf(q4.w, k4.w, b4.w);
                hs0 += h0; hs1 += h1; hs2 += h2; hs3 += h3;
                acc[c].x = fmaf(tanh_apx(h0), mh, acc[c].x);
                acc[c].y = fmaf(tanh_apx(h1), mh, acc[c].y);
                acc[c].z = fmaf(tanh_apx(h2), mh, acc[c].z);
                acc[c].w = fmaf(tanh_apx(h3), mh, acc[c].w);
            }
            float hs = (hs0 + hs1) + (hs2 + hs3);       // this half's 32-ch sum
            hs += __shfl_xor_sync(0xffffffffu, hs, 16); // full 64-ch sum
            if (half == 0) arow[t * TJ + jj] = 2.0f * (hs - ssum) * m;
            msum += m;
        }
        __syncthreads();   // all warps done reading tile t before it is overwritten
    }

    // reduce over the 16 lj lanes (stay within channel half)
    #pragma unroll
    for (int s = 1; s < 16; s <<= 1) {
        msum += __shfl_xor_sync(0xffffffffu, msum, s);
        #pragma unroll
        for (int c = 0; c < 8; ++c) {
            acc[c].x += __shfl_xor_sync(0xffffffffu, acc[c].x, s);
            acc[c].y += __shfl_xor_sync(0xffffffffu, acc[c].y, s);
            acc[c].z += __shfl_xor_sync(0xffffffffu, acc[c].z, s);
            acc[c].w += __shfl_xor_sync(0xffffffffu, acc[c].w, s);
        }
    }
    if (lj == 0) {   // lanes 0 and 16: write this (row, jh, half) partial
        float4* dst = (float4*)&sacc[rowl][jh][half * 32];
        #pragma unroll
        for (int c = 0; c < 8; ++c) dst[c] = acc[c];
        if (half == 0) smsum[rowl][jh] = msum;
    }
    __syncthreads();

    // 128 threads = ROWS(2) x C_(64): combine the two j-half warps, finalize
    {
        const int r  = tid >> 6;
        const int ch = tid & 63;
        const float ms = smsum[r][0] + smsum[r][1];
        const float v  = sacc[r][0][ch] + sacc[r][1][ch];
        out[(size_t)(blockIdx.x * ROWS + r) * C_ + ch] =
            (v + 0.5f * ms) * __fdividef(1.0f, ms);
    }
}

extern "C" void kernel_launch(void* const* d_in, const int* in_sizes, int n_in,
                              void* d_out, int out_size) {
    const float* Q    = (const float*)d_in[0];
    const float* K    = (const float*)d_in[1];
    const float* bias = (const float*)d_in[2];
    const float* mask = (const float*)d_in[3];
    float* out  = (float*)d_out;                       // [B,I,C] first
    float* attn = (float*)d_out + (size_t)B_*I_*C_;    // [B,I,J] second

    dim3 grid(B_ * I_ / ROWS);
    dim3 block(THREADS);
    fused_attn_mlp_kernel<<<grid, block>>>(Q, K, bias, mask, out, attn);
}

// round 6
// speedup vs baseline: 1.8146x; 1.8146x over previous
#include <cuda_runtime.h>
#include <cstdint>

#define B_      2
#define I_      1024
#define J_      1024
#define C_      64
#define TJ      32
#define NT      (J_/TJ)     // 32
#define ROWS    2
#define THREADS 64
#define KPAD    17          // float4 per K row in smem (conflict-free)

__device__ __forceinline__ float tanh_apx(float x) {
    float y; asm("tanh.approx.f32 %0, %1;" : "=f"(y) : "f"(x)); return y;
}
__device__ __forceinline__ void cp16(uint32_t s, const void* g) {
    asm volatile("cp.async.cg.shared.global [%0], [%1], 16;" :: "r"(s), "l"(g));
}
__device__ __forceinline__ void cp_commit() { asm volatile("cp.async.commit_group;"); }
template<int N> __device__ __forceinline__ void cp_wait() {
    asm volatile("cp.async.wait_group %0;" :: "n"(N));
}

__global__ __launch_bounds__(THREADS, 7)
void fused_attn_mlp_kernel(const float* __restrict__ Q,
                           const float* __restrict__ K,
                           const float* __restrict__ bias,
                           const float* __restrict__ mask,
                           float* __restrict__ out,      // [B,I,C]
                           float* __restrict__ attn)     // [B,I,J]
{
    __shared__ __align__(16) float4 kbuf[2][TJ * KPAD];   // 2 x 8.7KB
    __shared__ __align__(16) float4 sbv[16];              // 0.5*bias

    const int tid  = threadIdx.x;
    const int lane = tid & 31;
    const int w    = tid >> 5;            // warp = local row (0/1)
    const int half = lane >> 4;           // 0: ch 0-31, 1: ch 32-63
    const int lj   = lane & 15;           // j subgroup index
    const int row  = blockIdx.x * ROWS + w;
    const int b    = row >> 10;
    const int h8   = half * 8;            // float4 offset of this channel half

    if (tid < C_) ((float*)sbv)[tid] = 0.5f * bias[tid];

    const uint32_t sb0 = (uint32_t)__cvta_generic_to_shared(&kbuf[0][0]);
    const uint32_t sb1 = (uint32_t)__cvta_generic_to_shared(&kbuf[1][0]);
    const float4* Kb = (const float4*)K + (size_t)b * J_ * 16;

    // prefetch tile 0: TJ*16 = 512 float4 / 64 thr = 8 per thread
    #pragma unroll
    for (int p = 0; p < (TJ * 16) / THREADS; ++p) {
        int idx = tid + p * THREADS;
        int r = idx >> 4, c = idx & 15;
        cp16(sb0 + (uint32_t)(r * KPAD + c) * 16, Kb + (size_t)r * 16 + c);
    }
    cp_commit();

    // q-half straight to registers (each lane loads its own 32 channels of its row)
    float4 qh[8];
    {
        const float4* qrow = (const float4*)(Q + (size_t)row * C_) + h8;
        #pragma unroll
        for (int c = 0; c < 8; ++c) {
            float4 v = qrow[c];
            qh[c] = make_float4(0.5f*v.x, 0.5f*v.y, 0.5f*v.z, 0.5f*v.w);
        }
    }

    __syncthreads();   // sbv visible

    float ssum = 0.f;
    #pragma unroll
    for (int c = 0; c < C_; ++c) ssum += ((const float*)sbv)[c];

    const float4* bp = &sbv[h8];   // loop-invariant; ptxas may hoist to regs

    float4 acc[8];
    #pragma unroll
    for (int c = 0; c < 8; ++c) acc[c] = make_float4(0.f, 0.f, 0.f, 0.f);
    float msum = 0.f;

    const float* mrow = mask + (size_t)row * J_;
    float*       arow = attn + (size_t)row * J_;

    for (int t = 0; t < NT; ++t) {
        const float m0 = mrow[t * TJ + lj];
        const float m1 = mrow[t * TJ + 16 + lj];

        if (t + 1 < NT) {
            const float4* src = Kb + (size_t)(t + 1) * TJ * 16;
            uint32_t dst = ((t + 1) & 1) ? sb1 : sb0;
            #pragma unroll
            for (int p = 0; p < (TJ * 16) / THREADS; ++p) {
                int idx = tid + p * THREADS;
                int r = idx >> 4, c = idx & 15;
                cp16(dst + (uint32_t)(r * KPAD + c) * 16, src + (size_t)r * 16 + c);
            }
            cp_commit();
            cp_wait<1>();
        } else {
            cp_wait<0>();
        }
        __syncthreads();

        const float4* kb = kbuf[t & 1];

        #pragma unroll
        for (int u = 0; u < 2; ++u) {
            const int jj = u * 16 + lj;
            const float m  = (u == 0) ? m0 : m1;
            const float mh = 0.5f * m;
            const float4* kr = kb + jj * KPAD + h8;

            float hs0 = 0.f, hs1 = 0.f, hs2 = 0.f, hs3 = 0.f;
            #pragma unroll
            for (int c = 0; c < 8; ++c) {
                const float4 k4 = kr[c];
                const float4 b4 = bp[c];
                const float h0 = fmaf(qh[c].x, k4.x, b4.x);
                const float h1 = fmaf(qh[c].y, k4.y, b4.y);
                const float h2 = fmaf(qh[c].z, k4.z, b4.z);
                const float h3 = fmaf(qh[c].w, k4.w, b4.w);
                hs0 += h0; hs1 += h1; hs2 += h2; hs3 += h3;
                acc[c].x = fmaf(tanh_apx(h0), mh, acc[c].x);
                acc[c].y = fmaf(tanh_apx(h1), mh, acc[c].y);
                acc[c].z = fmaf(tanh_apx(h2), mh, acc[c].z);
                acc[c].w = fmaf(tanh_apx(h3), mh, acc[c].w);
            }
            float hs = (hs0 + hs1) + (hs2 + hs3);       // this half's 32-ch sum
            hs += __shfl_xor_sync(0xffffffffu, hs, 16); // full 64-ch sum
            if (half == 0) arow[t * TJ + jj] = 2.0f * (hs - ssum) * m;
            msum += m;
        }
        __syncthreads();   // all lanes done reading tile t before overwrite
    }

    // reduce over the 16 lj lanes (channel halves stay separate; j-sets identical)
    #pragma unroll
    for (int s = 1; s < 16; s <<= 1) {
        msum += __shfl_xor_sync(0xffffffffu, msum, s);
        #pragma unroll
        for (int c = 0; c < 8; ++c) {
            acc[c].x += __shfl_xor_sync(0xffffffffu, acc[c].x, s);
            acc[c].y += __shfl_xor_sync(0xffffffffu, acc[c].y, s);
            acc[c].z += __shfl_xor_sync(0xffffffffu, acc[c].z, s);
            acc[c].w += __shfl_xor_sync(0xffffffffu, acc[c].w, s);
        }
    }

    if (lj == 0) {   // lane 0 writes ch 0-31, lane 16 writes ch 32-63
        const float hm  = 0.5f * msum;
        const float inv = __fdividef(1.0f, msum);
        float* orow = out + (size_t)row * C_ + half * 32;
        #pragma unroll
        for (int c = 0; c < 8; ++c) {
            float4 o;
            o.x = (acc[c].x + hm) * inv;
            o.y = (acc[c].y + hm) * inv;
            o.z = (acc[c].z + hm) * inv;
            o.w = (acc[c].w + hm) * inv;
            *(float4*)(orow + c * 4) = o;
        }
    }
}

extern "C" void kernel_launch(void* const* d_in, const int* in_sizes, int n_in,
                              void* d_out, int out_size) {
    const float* Q    = (const float*)d_in[0];
    const float* K    = (const float*)d_in[1];
    const float* bias = (const float*)d_in[2];
    const float* mask = (const float*)d_in[3];
    float* out  = (float*)d_out;                       // [B,I,C] first
    float* attn = (float*)d_out + (size_t)B_*I_*C_;    // [B,I,J] second

    dim3 grid(B_ * I_ / ROWS);
    dim3 block(THREADS);
    fused_attn_mlp_kernel<<<grid, block>>>(Q, K, bias, mask, out, attn);
}